// round 2
// baseline (speedup 1.0000x reference)
#include <cuda_runtime.h>

// Problem constants (from reference)
#define BER_F 0.02f
#define NBITS 9

#define BB 64
#define HC 32
#define WC 32
#define HF 64
#define WF 64
#define DD 128

#define NF (BB * HF * WF)          // 262144 fine indices
#define NC (BB * HC * WC)          // 65536 coarse indices
#define HWF (HF * WF)              // 4096
#define HWC (HC * WC)              // 1024
#define ROW_F (HWF * DD)           // 524288 floats per batch (fine part)
#define ROW_C (HWC * DD)           // 131072 floats per batch (coarse part)
#define ROW (ROW_F + ROW_C)        // 655360 floats per batch row

// One warp per index: lanes 0..8 build the flip mask via ballot, then all 32
// lanes copy 128 floats (one float4 each) codebook -> out. Both the codebook
// gather (512B contiguous) and the store (512B contiguous) are coalesced.
__global__ __launch_bounds__(256)
void awgn_channel_kernel(const int* __restrict__ idx_c,
                         const int* __restrict__ idx_f,
                         const float4* __restrict__ cb_c,   // [512][32] float4
                         const float4* __restrict__ cb_f,   // [512][32] float4
                         const float* __restrict__ u_c,     // [NC][9]
                         const float* __restrict__ u_f,     // [NF][9]
                         float4* __restrict__ out)          // [B][ROW] as float4
{
    const unsigned gtid = blockIdx.x * blockDim.x + threadIdx.x;
    const unsigned warp = gtid >> 5;
    const unsigned lane = threadIdx.x & 31;

    const int* __restrict__ idx;
    const float4* __restrict__ cb;
    const float* __restrict__ u;
    unsigned i;
    size_t out_f4;   // float4 offset into out

    if (warp < NF) {
        i   = warp;
        idx = idx_f;  cb = cb_f;  u = u_f;
        const unsigned b  = i / HWF;
        const unsigned hw = i - b * HWF;
        out_f4 = ((size_t)b * ROW + (size_t)hw * DD) >> 2;
    } else {
        i = warp - NF;
        if (i >= NC) return;
        idx = idx_c;  cb = cb_c;  u = u_c;
        const unsigned b  = i / HWC;
        const unsigned hw = i - b * HWC;
        out_f4 = ((size_t)b * ROW + ROW_F + (size_t)hw * DD) >> 2;
    }

    // Flip mask: lanes 0..8 read one uniform each; ballot packs the 9 bits.
    float uv = 1.0f;
    if (lane < NBITS) uv = u[(size_t)i * NBITS + lane];
    const unsigned flips = __ballot_sync(0xffffffffu, uv < BER_F);

    // XOR of 9-bit index with 9-bit mask stays in [0, 512): clip is a no-op.
    const int rx = (idx[i] ^ (int)flips) & 511;

    // 128 floats = 32 float4; one per lane.
    out[out_f4 + lane] = cb[(size_t)rx * (DD / 4) + lane];
}

extern "C" void kernel_launch(void* const* d_in, const int* in_sizes, int n_in,
                              void* d_out, int out_size)
{
    const int*    idx_c = (const int*)d_in[0];
    const int*    idx_f = (const int*)d_in[1];
    const float4* cb_c  = (const float4*)d_in[2];
    const float4* cb_f  = (const float4*)d_in[3];
    const float*  u_c   = (const float*)d_in[4];
    const float*  u_f   = (const float*)d_in[5];
    float4*       out   = (float4*)d_out;

    const unsigned total_warps = NF + NC;               // 327680
    const unsigned threads = 256;                        // 8 warps/block
    const unsigned blocks = (total_warps * 32 + threads - 1) / threads;  // 40960

    awgn_channel_kernel<<<blocks, threads>>>(idx_c, idx_f, cb_c, cb_f, u_c, u_f, out);
}

// round 3
// speedup vs baseline: 1.4286x; 1.4286x over previous
#include <cuda_runtime.h>

// Problem constants (from reference)
#define BER_F 0.02f
#define NBITS 9

#define BB 64
#define HC 32
#define WC 32
#define HF 64
#define WF 64
#define DD 128

#define NF (BB * HF * WF)          // 262144 fine indices
#define NC (BB * HC * WC)          // 65536 coarse indices
#define NTOT (NF + NC)             // 327680 total indices
#define HWF (HF * WF)              // 4096
#define HWC (HC * WC)              // 1024
#define ROW_F (HWF * DD)           // 524288 floats per batch (fine part)
#define ROW_C (HWC * DD)           // 131072 floats per batch (coarse part)
#define ROW (ROW_F + ROW_C)        // 655360 floats per batch row

#define IPW 3                      // indices per warp (3*9=27 ballot bits)

// Each warp handles 3 indices. Lanes 0..26 read one uniform each (lane = j*9+k
// -> index j, bit k); one ballot produces all three 9-bit flip masks. Then 3
// independent idx loads -> 3 independent codebook gathers -> 3 stores, batched
// for MLP=3. Gather and store are each 512B contiguous per warp per index.
__global__ __launch_bounds__(256)
void awgn_channel_kernel(const int* __restrict__ idx_c,
                         const int* __restrict__ idx_f,
                         const float4* __restrict__ cb_c,   // [512][32] float4
                         const float4* __restrict__ cb_f,   // [512][32] float4
                         const float* __restrict__ u_c,     // [NC][9]
                         const float* __restrict__ u_f,     // [NF][9]
                         float4* __restrict__ out)          // [B][ROW] as float4
{
    const unsigned gtid = blockIdx.x * blockDim.x + threadIdx.x;
    const unsigned warp = gtid >> 5;
    const unsigned lane = threadIdx.x & 31;
    const unsigned i0 = warp * IPW;
    if (i0 >= NTOT) return;

    // --- flip-mask uniforms: lanes 0..26, one per (index j, bit k) ---
    float uv = 1.0f;
    if (lane < IPW * NBITS) {
        const unsigned j = lane / NBITS;          // 0..2
        const unsigned k = lane - j * NBITS;      // 0..8
        const unsigned g = i0 + j;
        if (g < NTOT) {
            uv = (g < NF) ? u_f[(size_t)g * NBITS + k]
                          : u_c[(size_t)(g - NF) * NBITS + k];
        }
    }
    const unsigned ballot = __ballot_sync(0xffffffffu, uv < BER_F);

    // --- per-index: resolve region, load idx, compute rx and out offset ---
    int rx[IPW];
    size_t ofs[IPW];
    const float4* cbp[IPW];
    bool valid[IPW];

    #pragma unroll
    for (int j = 0; j < IPW; j++) {
        const unsigned g = i0 + j;
        valid[j] = (g < NTOT);
        unsigned flips = (ballot >> (NBITS * j)) & 511u;
        if (!valid[j]) { rx[j] = 0; ofs[j] = 0; cbp[j] = cb_f; continue; }
        if (g < NF) {
            const unsigned b  = g >> 12;            // / HWF (4096)
            const unsigned hw = g & (HWF - 1);
            ofs[j] = ((size_t)b * ROW + (size_t)hw * DD) >> 2;
            cbp[j] = cb_f;
            rx[j] = (idx_f[g] ^ (int)flips) & 511;
        } else {
            const unsigned gc = g - NF;
            const unsigned b  = gc >> 10;           // / HWC (1024)
            const unsigned hw = gc & (HWC - 1);
            ofs[j] = ((size_t)b * ROW + ROW_F + (size_t)hw * DD) >> 2;
            cbp[j] = cb_c;
            rx[j] = (idx_c[gc] ^ (int)flips) & 511;
        }
    }

    // --- batched gathers (3 independent LDG.128 in flight) ---
    float4 val[IPW];
    #pragma unroll
    for (int j = 0; j < IPW; j++)
        val[j] = cbp[j][(size_t)rx[j] * (DD / 4) + lane];

    // --- batched stores ---
    #pragma unroll
    for (int j = 0; j < IPW; j++)
        if (valid[j]) out[ofs[j] + lane] = val[j];
}

extern "C" void kernel_launch(void* const* d_in, const int* in_sizes, int n_in,
                              void* d_out, int out_size)
{
    const int*    idx_c = (const int*)d_in[0];
    const int*    idx_f = (const int*)d_in[1];
    const float4* cb_c  = (const float4*)d_in[2];
    const float4* cb_f  = (const float4*)d_in[3];
    const float*  u_c   = (const float*)d_in[4];
    const float*  u_f   = (const float*)d_in[5];
    float4*       out   = (float4*)d_out;

    const unsigned total_warps = (NTOT + IPW - 1) / IPW;      // 109227
    const unsigned threads = 256;                              // 8 warps/block
    const unsigned blocks = (total_warps * 32 + threads - 1) / threads;

    awgn_channel_kernel<<<blocks, threads>>>(idx_c, idx_f, cb_c, cb_f, u_c, u_f, out);
}

// round 4
// speedup vs baseline: 1.4918x; 1.0443x over previous
#include <cuda_runtime.h>

// Problem constants (from reference)
#define BER_F 0.02f
#define NBITS 9

#define BB 64
#define HC 32
#define WC 32
#define HF 64
#define WF 64
#define DD 128

#define NF (BB * HF * WF)          // 262144 fine indices
#define NC (BB * HC * WC)          // 65536 coarse indices
#define NTOT (NF + NC)             // 327680 = 65536 * 5  -> IPW=5 exact
#define HWF (HF * WF)              // 4096
#define HWC (HC * WC)              // 1024
#define ROW4 (163840u)             // float4 per batch row (655360/4)
#define ROWF4 (131072u)            // float4 fine part per row (524288/4)

#define IPW 5                      // indices per warp; NTOT % (32*... ) exact

// Each warp handles 5 consecutive indices (no tail: NTOT = 65536*5).
// Flip masks: 45 uniform samples via two ballots (27 + 18 bits).
// Then 5 independent idx loads -> 5 independent 512B codebook gathers ->
// 5 contiguous 512B stores, loads batched ahead of stores for MLP=5.
__global__ __launch_bounds__(256)
void awgn_channel_kernel(const int* __restrict__ idx_c,
                         const int* __restrict__ idx_f,
                         const float4* __restrict__ cb_c,   // [512][32] float4
                         const float4* __restrict__ cb_f,   // [512][32] float4
                         const float* __restrict__ u_c,     // [NC][9]
                         const float* __restrict__ u_f,     // [NF][9]
                         float4* __restrict__ out)          // [B][ROW] as float4
{
    const unsigned gtid = blockIdx.x * blockDim.x + threadIdx.x;
    const unsigned warp = gtid >> 5;
    const unsigned lane = threadIdx.x & 31;
    const unsigned i0 = warp * IPW;           // < NTOT always (exact grid)

    // --- flip-mask uniforms ---
    // ballot0: lanes 0..26 -> (j = lane/9 in 0..2, bit k = lane%9)
    // ballot1: lanes 0..17 -> (j = 3 + lane/9 in 3..4, bit k = lane%9)
    float uv0 = 1.0f, uv1 = 1.0f;
    {
        const unsigned jj = lane / NBITS;     // 0..3
        const unsigned k  = lane - jj * NBITS;
        if (lane < 3 * NBITS) {
            const unsigned g = i0 + jj;
            uv0 = (g < NF) ? u_f[(size_t)g * NBITS + k]
                           : u_c[(size_t)(g - NF) * NBITS + k];
        }
        if (lane < 2 * NBITS) {
            const unsigned g = i0 + 3 + jj;
            uv1 = (g < NF) ? u_f[(size_t)g * NBITS + k]
                           : u_c[(size_t)(g - NF) * NBITS + k];
        }
    }
    const unsigned b0 = __ballot_sync(0xffffffffu, uv0 < BER_F);
    const unsigned b1 = __ballot_sync(0xffffffffu, uv1 < BER_F);

    // --- per-index: region, idx load, rx, out offset (32-bit float4 units) ---
    int      rx[IPW];          // 9-bit received index
    unsigned ofs[IPW];         // float4 offset into out
    unsigned fine[IPW];        // region flag

    #pragma unroll
    for (int j = 0; j < IPW; j++) {
        const unsigned g = i0 + (unsigned)j;
        const unsigned flips = (j < 3) ? ((b0 >> (NBITS * j)) & 511u)
                                       : ((b1 >> (NBITS * (j - 3))) & 511u);
        if (g < NF) {
            fine[j] = 1u;
            const unsigned b  = g >> 12;            // / 4096
            const unsigned hw = g & (HWF - 1);
            ofs[j] = b * ROW4 + hw * (DD / 4);
            rx[j]  = (idx_f[g] ^ (int)flips) & 511;
        } else {
            fine[j] = 0u;
            const unsigned gc = g - NF;
            const unsigned b  = gc >> 10;           // / 1024
            const unsigned hw = gc & (HWC - 1);
            ofs[j] = b * ROW4 + ROWF4 + hw * (DD / 4);
            rx[j]  = (idx_c[gc] ^ (int)flips) & 511;
        }
    }

    // --- batched gathers: 5 independent LDG.128 in flight per thread ---
    float4 val[IPW];
    #pragma unroll
    for (int j = 0; j < IPW; j++) {
        const float4* cb = fine[j] ? cb_f : cb_c;
        val[j] = cb[(unsigned)rx[j] * (DD / 4) + lane];
    }

    // --- batched stores (contiguous 512B per index) ---
    #pragma unroll
    for (int j = 0; j < IPW; j++)
        out[ofs[j] + lane] = val[j];
}

extern "C" void kernel_launch(void* const* d_in, const int* in_sizes, int n_in,
                              void* d_out, int out_size)
{
    const int*    idx_c = (const int*)d_in[0];
    const int*    idx_f = (const int*)d_in[1];
    const float4* cb_c  = (const float4*)d_in[2];
    const float4* cb_f  = (const float4*)d_in[3];
    const float*  u_c   = (const float*)d_in[4];
    const float*  u_f   = (const float*)d_in[5];
    float4*       out   = (float4*)d_out;

    const unsigned total_warps = NTOT / IPW;                   // 65536 exact
    const unsigned threads = 256;                               // 8 warps/block
    const unsigned blocks = total_warps * 32 / threads;         // 8192 exact

    awgn_channel_kernel<<<blocks, threads>>>(idx_c, idx_f, cb_c, cb_f, u_c, u_f, out);
}

// round 6
// speedup vs baseline: 1.6830x; 1.1281x over previous
#include <cuda_runtime.h>

// Problem constants (from reference)
#define BER_F 0.02f
#define NBITS 9

#define NF 262144                  // 64*64*64 fine indices
#define NC 65536                   // 64*32*32 coarse indices
#define NTOT 327680
#define HWF 4096
#define HWC 1024
#define ROW4  163840u              // float4 per output batch row
#define ROWF4 131072u              // float4 fine part per row
#define DD4   32u                  // float4 per D=128 vector

#define TPB 128
#define IPB 128                    // indices per block (NF % IPB == 0)
#define NBLK   (NTOT / IPB)        // 2560 blocks, exact
#define NBLK_F (NF / IPB)          // 2048 fine blocks

// Two-phase: phase 1 computes all rx for the block's 128 indices with
// massively parallel coalesced loads (no ballot, no DRAM load in any
// recurring chain); phase 2 is a pure gather->store copy engine with
// 8-deep MLP per warp. Each block is entirely fine or entirely coarse.
__global__ __launch_bounds__(TPB)
void awgn_channel_kernel(const int* __restrict__ idx_c,
                         const int* __restrict__ idx_f,
                         const float4* __restrict__ cb_c,   // [512][32] float4
                         const float4* __restrict__ cb_f,   // [512][32] float4
                         const float* __restrict__ u_c,     // [NC][9]
                         const float* __restrict__ u_f,     // [NF][9]
                         float4* __restrict__ out)
{
    __shared__ float su[IPB * NBITS];   // 4608 B staged uniforms
    __shared__ int   srx[IPB];          // received indices

    const unsigned tid = threadIdx.x;
    const bool fine = (blockIdx.x < NBLK_F);

    const float*  u;
    const int*    idxp;
    const float4* cb;
    unsigned gbase;   // base index within region
    unsigned obase;   // float4 offset of this block's first output vector
    if (fine) {
        gbase = blockIdx.x * IPB;
        u = u_f;  idxp = idx_f;  cb = cb_f;
        obase = (gbase >> 12) * ROW4 + (gbase & (HWF - 1)) * DD4;
    } else {
        gbase = blockIdx.x * IPB - NF;
        u = u_c;  idxp = idx_c;  cb = cb_c;
        obase = (gbase >> 10) * ROW4 + ROWF4 + (gbase & (HWC - 1)) * DD4;
    }

    // --- phase 1a: stage u coalesced (9 loads/thread, all independent) ---
    const float* ub = u + (size_t)gbase * NBITS;
    #pragma unroll
    for (int i = 0; i < NBITS; i++)
        su[tid + i * TPB] = ub[tid + i * TPB];

    // own idx load (independent of staging; issued before the barrier)
    const int myidx = idxp[gbase + tid];
    __syncthreads();

    // --- phase 1b: per-thread 9-bit flip mask, rx to smem ---
    // su[tid*9+k]: 9 coprime 32 -> conflict-free within a warp.
    unsigned m = 0;
    #pragma unroll
    for (int k = 0; k < NBITS; k++)
        m |= (su[tid * NBITS + k] < BER_F) ? (1u << k) : 0u;
    srx[tid] = (myidx ^ (int)m) & 511;   // XOR of 9-bit values: clip no-op
    __syncthreads();

    // --- phase 2: warp w copies indices [w*32, w*32+32) ---
    const unsigned w = tid >> 5, lane = tid & 31;
    const float4* cbl = cb + lane;
    float4* ol = out + obase + lane;

    #pragma unroll 1
    for (int t = 0; t < 32; t += 8) {
        int    r[8];
        float4 v[8];
        #pragma unroll
        for (int q = 0; q < 8; q++)        // LDS broadcast (uniform addr)
            r[q] = srx[w * 32 + t + q];
        #pragma unroll
        for (int q = 0; q < 8; q++)        // 8 independent 512B gathers
            v[q] = __ldg(&cbl[(unsigned)r[q] * DD4]);
        #pragma unroll
        for (int q = 0; q < 8; q++)        // streaming stores, never re-read
            __stcs(&ol[(unsigned)(w * 32 + t + q) * DD4], v[q]);
    }
}

extern "C" void kernel_launch(void* const* d_in, const int* in_sizes, int n_in,
                              void* d_out, int out_size)
{
    const int*    idx_c = (const int*)d_in[0];
    const int*    idx_f = (const int*)d_in[1];
    const float4* cb_c  = (const float4*)d_in[2];
    const float4* cb_f  = (const float4*)d_in[3];
    const float*  u_c   = (const float*)d_in[4];
    const float*  u_f   = (const float*)d_in[5];
    float4*       out   = (float4*)d_out;

    awgn_channel_kernel<<<NBLK, TPB>>>(idx_c, idx_f, cb_c, cb_f, u_c, u_f, out);
}